// round 5
// baseline (speedup 1.0000x reference)
#include <cuda_runtime.h>
#include <cstdint>

#define NPTS 16384
#define DIM  64
#define MB   64                  // rows per CTA
#define NBT  128                 // cols per tile
#define NT   256                 // threads
#define TILES (NPTS / NBT)       // 128 tiles, full column sweep
#define RS   68                  // padded smem row stride (floats)

// smem (floats): A0 | A1 | B[2] | sqs
#define OFF_A0 0
#define OFF_A1 (MB * RS)                 // 4352
#define OFF_B  (2 * MB * RS)             // 8704
#define BBUF   (NBT * RS)                // 8704
#define OFF_SQ (OFF_B + 2 * BBUF)        // 26112
#define SMEM_FLOATS (OFF_SQ + NBT)
#define SMEM_BYTES (SMEM_FLOATS * 4)     // 104960 -> 2 CTAs/SM

__device__ float g_sq[NPTS];

// ---------------- helpers ----------------
__device__ __forceinline__ uint32_t cvt_tf32(float x) {
    uint32_t u;
    asm("cvt.rna.tf32.f32 %0, %1;" : "=r"(u) : "f"(x));
    return u;
}
__device__ __forceinline__ void cp16(uint32_t dst, const void* src) {
    asm volatile("cp.async.cg.shared.global [%0], [%1], 16;" :: "r"(dst), "l"(src));
}
#define CP_COMMIT() asm volatile("cp.async.commit_group;")
#define CP_WAIT(n)  asm volatile("cp.async.wait_group %0;" :: "n"(n))

#define MMA(c, a, b) \
    asm volatile("mma.sync.aligned.m16n8k8.row.col.f32.tf32.tf32.f32 " \
        "{%0,%1,%2,%3},{%4,%5,%6,%7},{%8,%9},{%0,%1,%2,%3};" \
        : "+f"((c)[0]), "+f"((c)[1]), "+f"((c)[2]), "+f"((c)[3]) \
        : "r"((a)[0]), "r"((a)[1]), "r"((a)[2]), "r"((a)[3]), \
          "r"((b)[0]), "r"((b)[1]))

// ---------------- squared norms ----------------
__global__ void sq_kernel(const float* __restrict__ X) {
    int warp = (blockIdx.x * blockDim.x + threadIdx.x) >> 5;
    int lane = threadIdx.x & 31;
    if (warp >= NPTS) return;
    const float* row = X + (size_t)warp * DIM;
    float a = row[lane], b = row[lane + 32];
    float s = a * a + b * b;
    #pragma unroll
    for (int o = 16; o; o >>= 1) s += __shfl_xor_sync(0xffffffffu, s, o);
    if (lane == 0) g_sq[warp] = s;
}

// ---------------- main kernel ----------------
__global__ void __launch_bounds__(NT, 2)
knn_kernel(const float* __restrict__ X, float* __restrict__ out) {
    extern __shared__ float sm[];
    uint32_t smb;
    asm("{ .reg .u64 t; cvta.to.shared.u64 t, %1; cvt.u32.u64 %0, t; }"
        : "=r"(smb) : "l"(sm));

    const int tid  = threadIdx.x;
    const int lane = tid & 31;
    const int wid  = tid >> 5;
    const int wm   = wid >> 2;          // 0..1 -> rows wm*32
    const int wn   = wid & 3;           // 0..3 -> cols wn*32
    const int lg   = lane >> 2;         // 0..7
    const int lt   = lane & 3;          // 0..3
    const int row0 = blockIdx.x * MB;

    // ---- A setup: LDG fp32, split to tf32 planes in-register, store both ----
    #pragma unroll
    for (int i = 0; i < 4; i++) {
        int idx = i * NT + tid;          // 64 rows x 16 quads
        int r = idx >> 4, q = idx & 15;
        float4 v = *(const float4*)(X + (size_t)(row0 + r) * DIM + q * 4);
        float4 p0, p1;
        p0.x = __uint_as_float(cvt_tf32(v.x)); p1.x = __uint_as_float(cvt_tf32(v.x - p0.x));
        p0.y = __uint_as_float(cvt_tf32(v.y)); p1.y = __uint_as_float(cvt_tf32(v.y - p0.y));
        p0.z = __uint_as_float(cvt_tf32(v.z)); p1.z = __uint_as_float(cvt_tf32(v.z - p0.z));
        p0.w = __uint_as_float(cvt_tf32(v.w)); p1.w = __uint_as_float(cvt_tf32(v.w - p0.w));
        *(float4*)(sm + OFF_A0 + r * RS + q * 4) = p0;
        *(float4*)(sm + OFF_A1 + r * RS + q * 4) = p1;
    }

    // ---- B tiles 0,1 via cp.async ----
    #pragma unroll
    for (int i = 0; i < 8; i++) {
        int idx = i * NT + tid;
        int r = idx >> 4, q = idx & 15;
        cp16(smb + (OFF_B + r * RS + q * 4) * 4, &X[(size_t)r * DIM + q * 4]);
    }
    CP_COMMIT();
    #pragma unroll
    for (int i = 0; i < 8; i++) {
        int idx = i * NT + tid;
        int r = idx >> 4, q = idx & 15;
        cp16(smb + (OFF_B + BBUF + r * RS + q * 4) * 4, &X[(size_t)(NBT + r) * DIM + q * 4]);
    }
    CP_COMMIT();

    const uint32_t* A0u = (const uint32_t*)(sm + OFF_A0);
    const uint32_t* A1u = (const uint32_t*)(sm + OFF_A1);
    float* sqs = sm + OFF_SQ;

    float mn[4];
    int   mi[4];
    #pragma unroll
    for (int s = 0; s < 4; s++) { mn[s] = 3.402823466e38f; mi[s] = 0; }

    const int abase = (wm * 32 + lg) * RS + lt;     // + mf*16*RS (+8*RS), + kb (+4)

    for (int t = 0; t < TILES; t++) {
        const float* Bs = sm + OFF_B + (t & 1) * BBUF;
        const int cb = t * NBT;

        if (tid < NBT) sqs[tid] = g_sq[cb + tid];
        if (t + 1 < TILES) { CP_WAIT(1); } else { CP_WAIT(0); }
        __syncthreads();

        float acc[2][4][4];
        #pragma unroll
        for (int mf = 0; mf < 2; mf++)
            #pragma unroll
            for (int nf = 0; nf < 4; nf++)
                #pragma unroll
                for (int r = 0; r < 4; r++) acc[mf][nf][r] = 0.f;

        #pragma unroll
        for (int k8 = 0; k8 < 8; k8++) {
            const int kb = k8 * 8;
            uint32_t ta0[2][4], ta1[2][4];
            #pragma unroll
            for (int mf = 0; mf < 2; mf++) {
                int b = abase + mf * 16 * RS + kb;
                ta0[mf][0] = A0u[b];
                ta0[mf][1] = A0u[b + 8 * RS];
                ta0[mf][2] = A0u[b + 4];
                ta0[mf][3] = A0u[b + 8 * RS + 4];
                ta1[mf][0] = A1u[b];
                ta1[mf][1] = A1u[b + 8 * RS];
                ta1[mf][2] = A1u[b + 4];
                ta1[mf][3] = A1u[b + 8 * RS + 4];
            }
            uint32_t u0[4][2], u1[4][2];
            #pragma unroll
            for (int nf = 0; nf < 4; nf++) {
                int cbs = (wn * 32 + nf * 8 + lg) * RS + kb + lt;
                float b0 = Bs[cbs];
                float b1 = Bs[cbs + 4];
                u0[nf][0] = cvt_tf32(b0);
                u1[nf][0] = cvt_tf32(b0 - __uint_as_float(u0[nf][0]));
                u0[nf][1] = cvt_tf32(b1);
                u1[nf][1] = cvt_tf32(b1 - __uint_as_float(u0[nf][1]));
            }
            // product-major: same-acc reuse distance = 8 mma
            #pragma unroll
            for (int mf = 0; mf < 2; mf++)
                #pragma unroll
                for (int nf = 0; nf < 4; nf++) MMA(acc[mf][nf], ta0[mf], u0[nf]);
            #pragma unroll
            for (int mf = 0; mf < 2; mf++)
                #pragma unroll
                for (int nf = 0; nf < 4; nf++) MMA(acc[mf][nf], ta0[mf], u1[nf]);
            #pragma unroll
            for (int mf = 0; mf < 2; mf++)
                #pragma unroll
                for (int nf = 0; nf < 4; nf++) MMA(acc[mf][nf], ta1[mf], u0[nf]);
        }

        // ---- epilogue: argmin of (sb - 2*dot); self excluded ----
        #pragma unroll
        for (int mf = 0; mf < 2; mf++) {
            const int ig = row0 + wm * 32 + mf * 16 + lg;   // +8 for h=1
            #pragma unroll
            for (int nf = 0; nf < 4; nf++) {
                const int lc = wn * 32 + nf * 8 + 2 * lt;
                const float sb0 = sqs[lc], sb1 = sqs[lc + 1];
                const int j0 = cb + lc, j1 = j0 + 1;
                float v;
                v = fmaf(-2.f, acc[mf][nf][0], sb0);
                if (j0 != ig && v < mn[mf * 2]) { mn[mf * 2] = v; mi[mf * 2] = j0; }
                v = fmaf(-2.f, acc[mf][nf][1], sb1);
                if (j1 != ig && v < mn[mf * 2]) { mn[mf * 2] = v; mi[mf * 2] = j1; }
                v = fmaf(-2.f, acc[mf][nf][2], sb0);
                if (j0 != ig + 8 && v < mn[mf * 2 + 1]) { mn[mf * 2 + 1] = v; mi[mf * 2 + 1] = j0; }
                v = fmaf(-2.f, acc[mf][nf][3], sb1);
                if (j1 != ig + 8 && v < mn[mf * 2 + 1]) { mn[mf * 2 + 1] = v; mi[mf * 2 + 1] = j1; }
            }
        }

        // ---- fused zero-fill: warp owns 8 rows, 512B/row wavefront ----
        {
            const float4 z4 = make_float4(0.f, 0.f, 0.f, 0.f);
            float4* p = (float4*)(out + (size_t)(row0 + wid * 8) * NPTS + cb) + lane;
            #pragma unroll
            for (int i = 0; i < 8; i++) {
                *p = z4;
                p += NPTS / 4;
            }
        }

        __syncthreads();
        if (t + 2 < TILES) {
            #pragma unroll
            for (int i = 0; i < 8; i++) {
                int idx = i * NT + tid;
                int r = idx >> 4, q = idx & 15;
                cp16(smb + (OFF_B + (t & 1) * BBUF + r * RS + q * 4) * 4,
                     &X[(size_t)((t + 2) * NBT + r) * DIM + q * 4]);
            }
            CP_COMMIT();
        }
    }

    // ---- cross-warp reduction (16 partials per row), direct output write ----
    float* redv = sm;                        // reuse A region
    int*   redi = (int*)(sm + MB * 16);
    #pragma unroll
    for (int s = 0; s < 4; s++) {
        int rloc = wm * 32 + (s >> 1) * 16 + (s & 1) * 8 + lg;
        redv[rloc * 16 + wn * 4 + lt] = mn[s];
        redi[rloc * 16 + wn * 4 + lt] = mi[s];
    }
    __syncthreads();
    if (tid < MB) {
        float bv = redv[tid * 16];
        int   bi = redi[tid * 16];
        #pragma unroll
        for (int x = 1; x < 16; x++) {
            float v = redv[tid * 16 + x];
            int   i = redi[tid * 16 + x];
            if (v < bv || (v == bv && i < bi)) { bv = v; bi = i; }
        }
        size_t rg = row0 + tid;
        out[rg * NPTS + rg] = 1.0f;     // self (rank-1 in reference)
        out[rg * NPTS + bi] = 1.0f;     // nearest neighbor
    }
}

extern "C" void kernel_launch(void* const* d_in, const int* in_sizes, int n_in,
                              void* d_out, int out_size) {
    const float* X = (const float*)d_in[0];
    float* out = (float*)d_out;
    cudaFuncSetAttribute(knn_kernel, cudaFuncAttributeMaxDynamicSharedMemorySize, SMEM_BYTES);
    sq_kernel<<<NPTS / 8, 256>>>(X);
    knn_kernel<<<NPTS / MB, NT, SMEM_BYTES>>>(X, out);
}

// round 6
// speedup vs baseline: 1.3862x; 1.3862x over previous
#include <cuda_runtime.h>
#include <cstdint>

#define NPTS 16384
#define DIM  64
#define MB   64                  // rows per CTA
#define NBT  128                 // cols per tile
#define NT   256                 // threads
#define NCHUNK 8
#define COLS_PER_CTA (NPTS / NCHUNK)   // 2048
#define TILES (COLS_PER_CTA / NBT)     // 16
#define RS   68                  // padded B smem row stride (floats)

// smem (floats): AF (fragmented A, 2 planes) | B[2] | sqs
#define OFF_AF 0
#define AF_FLOATS 8192                   // 2pl * 8k8 * 2wm * 2mf * 128
#define OFF_B  AF_FLOATS
#define BBUF   (NBT * RS)                // 8704
#define OFF_SQ (OFF_B + 2 * BBUF)        // 25600
#define SMEM_FLOATS (OFF_SQ + NBT)
#define SMEM_BYTES (SMEM_FLOATS * 4)     // 102912 -> 2 CTAs/SM

__device__ float g_sq[NPTS];
__device__ unsigned long long g_key[NPTS];

// ---------------- helpers ----------------
__device__ __forceinline__ uint32_t cvt_tf32(float x) {
    uint32_t u;
    asm("cvt.rna.tf32.f32 %0, %1;" : "=r"(u) : "f"(x));
    return u;
}
__device__ __forceinline__ void cp16(uint32_t dst, const void* src) {
    asm volatile("cp.async.cg.shared.global [%0], [%1], 16;" :: "r"(dst), "l"(src));
}
#define CP_COMMIT() asm volatile("cp.async.commit_group;")
#define CP_WAIT(n)  asm volatile("cp.async.wait_group %0;" :: "n"(n))

#define MMA(c, a, b0, b1) \
    asm volatile("mma.sync.aligned.m16n8k8.row.col.f32.tf32.tf32.f32 " \
        "{%0,%1,%2,%3},{%4,%5,%6,%7},{%8,%9},{%0,%1,%2,%3};" \
        : "+f"((c)[0]), "+f"((c)[1]), "+f"((c)[2]), "+f"((c)[3]) \
        : "r"((a)[0]), "r"((a)[1]), "r"((a)[2]), "r"((a)[3]), \
          "r"(b0), "r"(b1))

// ---------------- small kernels ----------------
__global__ void sq_kernel(const float* __restrict__ X) {
    int warp = (blockIdx.x * blockDim.x + threadIdx.x) >> 5;
    int lane = threadIdx.x & 31;
    if (warp >= NPTS) return;
    const float* row = X + (size_t)warp * DIM;
    float a = row[lane], b = row[lane + 32];
    float s = a * a + b * b;
    #pragma unroll
    for (int o = 16; o; o >>= 1) s += __shfl_xor_sync(0xffffffffu, s, o);
    if (lane == 0) g_sq[warp] = s;
}

__global__ void init_kernel() {
    g_key[blockIdx.x * blockDim.x + threadIdx.x] = 0xFFFFFFFFFFFFFFFFull;
}

__global__ void final_kernel(float* __restrict__ out) {
    int row = blockIdx.x * blockDim.x + threadIdx.x;
    unsigned idx = (unsigned)(g_key[row] & 0xFFFFFFFFu);
    out[(size_t)row * NPTS + row] = 1.0f;
    out[(size_t)row * NPTS + idx] = 1.0f;
}

// ---------------- main kernel ----------------
__global__ void __launch_bounds__(NT, 2)
knn_kernel(const float* __restrict__ X, float* __restrict__ out) {
    extern __shared__ float sm[];
    uint32_t smb;
    asm("{ .reg .u64 t; cvta.to.shared.u64 t, %1; cvt.u32.u64 %0, t; }"
        : "=r"(smb) : "l"(sm));

    const int tid  = threadIdx.x;
    const int lane = tid & 31;
    const int wid  = tid >> 5;
    const int wm   = wid >> 2;          // 0..1 -> rows wm*32
    const int wn   = wid & 3;           // 0..3 -> cols wn*32
    const int lg   = lane >> 2;         // 0..7
    const int lt   = lane & 3;          // 0..3
    const int row0 = blockIdx.x * MB;
    const int col0 = blockIdx.y * COLS_PER_CTA;

    // ---- A setup: load fp32, split tf32 planes, store PRE-FRAGMENTED ----
    // dest tile index (pl,k8,wm,mf): 128 floats; within: lane*4 + c*2 + h
    #pragma unroll
    for (int i = 0; i < 16; i++) {
        int idx = i * NT + tid;          // 0..4095
        int r = idx >> 6, k = idx & 63;
        float x = X[(size_t)(row0 + r) * DIM + k];
        float a0 = __uint_as_float(cvt_tf32(x));
        float a1 = x - a0;               // tf32-truncated by mma read
        int wm_ = r >> 5, rr = r & 31;
        int mf_ = rr >> 4, h = (rr >> 3) & 1, lg_ = rr & 7;
        int k8_ = k >> 3, kk = k & 7;
        int c = kk >> 2, lt_ = kk & 3;
        int base = (((k8_ * 2 + wm_) * 2 + mf_) << 7) + (lg_ * 4 + lt_) * 4 + c * 2 + h;
        sm[OFF_AF + base] = a0;
        sm[OFF_AF + 4096 + base] = a1;
    }

    // ---- B tiles 0,1 via cp.async ----
    #pragma unroll
    for (int i = 0; i < 8; i++) {
        int idx = i * NT + tid;
        int r = idx >> 4, q = idx & 15;
        cp16(smb + (OFF_B + r * RS + q * 4) * 4, &X[(size_t)(col0 + r) * DIM + q * 4]);
    }
    CP_COMMIT();
    #pragma unroll
    for (int i = 0; i < 8; i++) {
        int idx = i * NT + tid;
        int r = idx >> 4, q = idx & 15;
        cp16(smb + (OFF_B + BBUF + r * RS + q * 4) * 4, &X[(size_t)(col0 + NBT + r) * DIM + q * 4]);
    }
    CP_COMMIT();

    const float4* AF4 = (const float4*)(sm + OFF_AF);
    float* sqs = sm + OFF_SQ;

    float mn[4];
    int   mi[4];
    #pragma unroll
    for (int s = 0; s < 4; s++) { mn[s] = 3.402823466e38f; mi[s] = 0; }

    for (int t = 0; t < TILES; t++) {
        const float* Bs = sm + OFF_B + (t & 1) * BBUF;
        const int cb = col0 + t * NBT;

        if (tid < NBT) sqs[tid] = g_sq[cb + tid];
        if (t + 1 < TILES) { CP_WAIT(1); } else { CP_WAIT(0); }
        __syncthreads();

        float acc[2][4][4];
        #pragma unroll
        for (int mf = 0; mf < 2; mf++)
            #pragma unroll
            for (int nf = 0; nf < 4; nf++)
                #pragma unroll
                for (int r = 0; r < 4; r++) acc[mf][nf][r] = 0.f;

        #pragma unroll
        for (int k8 = 0; k8 < 8; k8++) {
            // A fragments: 4 x LDS.128
            const int fb = ((k8 * 2 + wm) << 6) + lane;   // float4 index (tile=32 f4)
            float4 A0a = AF4[fb];
            float4 A0b = AF4[fb + 32];
            float4 A1a = AF4[fb + 1024];
            float4 A1b = AF4[fb + 1024 + 32];
            const uint32_t* ta0[2] = { (const uint32_t*)&A0a, (const uint32_t*)&A0b };
            const uint32_t* ta1[2] = { (const uint32_t*)&A1a, (const uint32_t*)&A1b };

            // B: raw fp32 loads + 1 cvt + 1 sub per value (b1 HW-truncated)
            const int kb = k8 * 8;
            uint32_t b0[4][2], b1[4][2];
            #pragma unroll
            for (int nf = 0; nf < 4; nf++) {
                int cbs = (wn * 32 + nf * 8 + lg) * RS + kb + lt;
                float blo = Bs[cbs];
                float bhi = Bs[cbs + 4];
                b0[nf][0] = cvt_tf32(blo);
                b1[nf][0] = __float_as_uint(blo - __uint_as_float(b0[nf][0]));
                b0[nf][1] = cvt_tf32(bhi);
                b1[nf][1] = __float_as_uint(bhi - __uint_as_float(b0[nf][1]));
            }
            // product-major: same-acc reuse distance = 8 mma
            #pragma unroll
            for (int mf = 0; mf < 2; mf++)
                #pragma unroll
                for (int nf = 0; nf < 4; nf++)
                    MMA(acc[mf][nf], ta0[mf], b0[nf][0], b0[nf][1]);
            #pragma unroll
            for (int mf = 0; mf < 2; mf++)
                #pragma unroll
                for (int nf = 0; nf < 4; nf++)
                    MMA(acc[mf][nf], ta0[mf], b1[nf][0], b1[nf][1]);
            #pragma unroll
            for (int mf = 0; mf < 2; mf++)
                #pragma unroll
                for (int nf = 0; nf < 4; nf++)
                    MMA(acc[mf][nf], ta1[mf], b0[nf][0], b0[nf][1]);
        }

        // ---- epilogue: argmin of (sb - 2*dot); self excluded ----
        #pragma unroll
        for (int mf = 0; mf < 2; mf++) {
            const int ig = row0 + wm * 32 + mf * 16 + lg;   // +8 for h=1
            #pragma unroll
            for (int nf = 0; nf < 4; nf++) {
                const int lc = wn * 32 + nf * 8 + 2 * lt;
                const float sb0 = sqs[lc], sb1 = sqs[lc + 1];
                const int j0 = cb + lc, j1 = j0 + 1;
                float v;
                v = fmaf(-2.f, acc[mf][nf][0], sb0);
                if (j0 != ig && v < mn[mf * 2]) { mn[mf * 2] = v; mi[mf * 2] = j0; }
                v = fmaf(-2.f, acc[mf][nf][1], sb1);
                if (j1 != ig && v < mn[mf * 2]) { mn[mf * 2] = v; mi[mf * 2] = j1; }
                v = fmaf(-2.f, acc[mf][nf][2], sb0);
                if (j0 != ig + 8 && v < mn[mf * 2 + 1]) { mn[mf * 2 + 1] = v; mi[mf * 2 + 1] = j0; }
                v = fmaf(-2.f, acc[mf][nf][3], sb1);
                if (j1 != ig + 8 && v < mn[mf * 2 + 1]) { mn[mf * 2 + 1] = v; mi[mf * 2 + 1] = j1; }
            }
        }

        // ---- fused zero-fill: warp owns 8 rows, 512B/row wavefront ----
        {
            const float4 z4 = make_float4(0.f, 0.f, 0.f, 0.f);
            float4* p = (float4*)(out + (size_t)(row0 + wid * 8) * NPTS + cb) + lane;
            #pragma unroll
            for (int i = 0; i < 8; i++) {
                *p = z4;
                p += NPTS / 4;
            }
        }

        __syncthreads();
        if (t + 2 < TILES) {
            #pragma unroll
            for (int i = 0; i < 8; i++) {
                int idx = i * NT + tid;
                int r = idx >> 4, q = idx & 15;
                cp16(smb + (OFF_B + (t & 1) * BBUF + r * RS + q * 4) * 4,
                     &X[(size_t)(col0 + (t + 2) * NBT + r) * DIM + q * 4]);
            }
            CP_COMMIT();
        }
    }

    // ---- cross-warp reduction (16 partials per row), then atomicMin merge ----
    float* redv = sm;                        // reuse AF region
    int*   redi = (int*)(sm + MB * 16);
    #pragma unroll
    for (int s = 0; s < 4; s++) {
        int rloc = wm * 32 + (s >> 1) * 16 + (s & 1) * 8 + lg;
        redv[rloc * 16 + wn * 4 + lt] = mn[s];
        redi[rloc * 16 + wn * 4 + lt] = mi[s];
    }
    __syncthreads();
    if (tid < MB) {
        float bv = redv[tid * 16];
        int   bi = redi[tid * 16];
        #pragma unroll
        for (int x = 1; x < 16; x++) {
            float v = redv[tid * 16 + x];
            int   i = redi[tid * 16 + x];
            if (v < bv || (v == bv && i < bi)) { bv = v; bi = i; }
        }
        uint32_t b = __float_as_uint(bv);
        b ^= (uint32_t)(((int32_t)b >> 31)) | 0x80000000u;   // monotonic map
        unsigned long long key = ((unsigned long long)b << 32) | (unsigned)bi;
        atomicMin(&g_key[row0 + tid], key);
    }
}

extern "C" void kernel_launch(void* const* d_in, const int* in_sizes, int n_in,
                              void* d_out, int out_size) {
    const float* X = (const float*)d_in[0];
    float* out = (float*)d_out;
    cudaFuncSetAttribute(knn_kernel, cudaFuncAttributeMaxDynamicSharedMemorySize, SMEM_BYTES);
    sq_kernel<<<NPTS / 8, 256>>>(X);
    init_kernel<<<NPTS / 256, 256>>>();
    knn_kernel<<<dim3(NPTS / MB, NCHUNK), NT, SMEM_BYTES>>>(X, out);
    final_kernel<<<NPTS / 256, 256>>>(out);
}

// round 7
// speedup vs baseline: 2.2990x; 1.6585x over previous
#include <cuda_runtime.h>
#include <cuda_fp16.h>
#include <cstdint>

#define NPTS 16384
#define DIM  64
#define MB   64                  // rows per CTA
#define NBT  128                 // cols per tile
#define NT   256                 // threads
#define NCHUNK 8
#define COLS_PER_CTA (NPTS / NCHUNK)   // 2048
#define TILES (COLS_PER_CTA / NBT)     // 16

// smem (uint32 units): AF (A fragments, 2 fp16 planes) | B[2] | sqs
#define OFF_AF 0
#define AF_U32 4096                      // 4s*2wm*2mf*2p*32lane*4
#define OFF_B  AF_U32
#define BBUF_U32 8192                    // 32KB per tile
#define OFF_SQ (OFF_B + 2 * BBUF_U32)    // 20480
#define SMEM_U32 (OFF_SQ + NBT)
#define SMEM_BYTES (SMEM_U32 * 4)        // 82432 -> 2 CTAs/SM

__device__ float g_sq[NPTS];
__device__ unsigned long long g_key[NPTS];
__device__ uint4 g_bf4[262144];          // 4MB pre-fragmented B (fits L2)

// ---------------- helpers ----------------
__device__ __forceinline__ void cp16(uint32_t dst, const void* src) {
    asm volatile("cp.async.cg.shared.global [%0], [%1], 16;" :: "r"(dst), "l"(src));
}
#define CP_COMMIT() asm volatile("cp.async.commit_group;")
#define CP_WAIT(n)  asm volatile("cp.async.wait_group %0;" :: "n"(n))

#define MMA16(c, a, b0, b1) \
    asm volatile("mma.sync.aligned.m16n8k16.row.col.f32.f16.f16.f32 " \
        "{%0,%1,%2,%3},{%4,%5,%6,%7},{%8,%9},{%0,%1,%2,%3};" \
        : "+f"((c)[0]), "+f"((c)[1]), "+f"((c)[2]), "+f"((c)[3]) \
        : "r"((a).x), "r"((a).y), "r"((a).z), "r"((a).w), \
          "r"(b0), "r"(b1))

__device__ __forceinline__ uint32_t pack_plane(float2 v, int p) {
    __half h0x = __float2half_rn(v.x);
    __half h0y = __float2half_rn(v.y);
    __half lx, ly;
    if (p == 0) { lx = h0x; ly = h0y; }
    else {
        lx = __float2half_rn(v.x - __half2float(h0x));
        ly = __float2half_rn(v.y - __half2float(h0y));
    }
    return (uint32_t)__half_as_ushort(lx) | ((uint32_t)__half_as_ushort(ly) << 16);
}

// ---------------- small kernels ----------------
__global__ void sq_kernel(const float* __restrict__ X) {
    int warp = (blockIdx.x * blockDim.x + threadIdx.x) >> 5;
    int lane = threadIdx.x & 31;
    if (warp >= NPTS) return;
    const float* row = X + (size_t)warp * DIM;
    float a = row[lane], b = row[lane + 32];
    float s = a * a + b * b;
    #pragma unroll
    for (int o = 16; o; o >>= 1) s += __shfl_xor_sync(0xffffffffu, s, o);
    if (lane == 0) g_sq[warp] = s;
}

// pre-fragment B planes: one uint4 (4 frag regs) per thread, coalesced stores
__global__ void prep_b(const float* __restrict__ X) {
    int gid = blockIdx.x * blockDim.x + threadIdx.x;   // 0..262143
    int lane = gid & 31;
    int r1 = gid >> 5;
    int npair = r1 & 7;
    int r2 = r1 >> 3;
    int p = r2 & 1;
    int r3 = r2 >> 1;
    int s = r3 & 3;
    int tile = r3 >> 2;
    int lg = lane >> 2, lt = lane & 3;
    int j0 = tile * 128 + npair * 16 + lg;
    int j1 = j0 + 8;
    int kb = s * 16 + 2 * lt;
    float2 e00 = *(const float2*)(X + (size_t)j0 * DIM + kb);
    float2 e01 = *(const float2*)(X + (size_t)j0 * DIM + kb + 8);
    float2 e10 = *(const float2*)(X + (size_t)j1 * DIM + kb);
    float2 e11 = *(const float2*)(X + (size_t)j1 * DIM + kb + 8);
    uint4 o;
    o.x = pack_plane(e00, p);   // sub0, reg0
    o.y = pack_plane(e01, p);   // sub0, reg1
    o.z = pack_plane(e10, p);   // sub1, reg0
    o.w = pack_plane(e11, p);   // sub1, reg1
    g_bf4[gid] = o;
}

__global__ void init_kernel() {
    g_key[blockIdx.x * blockDim.x + threadIdx.x] = 0xFFFFFFFFFFFFFFFFull;
}

__global__ void final_kernel(float* __restrict__ out) {
    int row = blockIdx.x * blockDim.x + threadIdx.x;
    unsigned idx = (unsigned)(g_key[row] & 0xFFFFFFFFu);
    out[(size_t)row * NPTS + row] = 1.0f;
    out[(size_t)row * NPTS + idx] = 1.0f;
}

// ---------------- main kernel ----------------
__global__ void __launch_bounds__(NT, 2)
knn_kernel(const float* __restrict__ X, float* __restrict__ out) {
    extern __shared__ uint32_t sm[];
    uint32_t smb;
    asm("{ .reg .u64 t; cvta.to.shared.u64 t, %1; cvt.u32.u64 %0, t; }"
        : "=r"(smb) : "l"(sm));

    const int tid  = threadIdx.x;
    const int lane = tid & 31;
    const int wid  = tid >> 5;
    const int wm   = wid >> 2;          // 0..1 -> rows wm*32
    const int wn   = wid & 3;           // 0..3 -> cols wn*32
    const int lg   = lane >> 2;         // 0..7
    const int lt   = lane & 3;          // 0..3
    const int row0 = blockIdx.x * MB;
    const int col0 = blockIdx.y * COLS_PER_CTA;

    // ---- A setup: load fp32, split fp16 planes, store pre-fragmented ----
    #pragma unroll
    for (int i = 0; i < 8; i++) {
        int item = i * NT + tid;         // 0..2047
        int r = item >> 5, k2 = item & 31;
        float2 v = *(const float2*)(X + (size_t)(row0 + r) * DIM + 2 * k2);
        uint32_t p0 = pack_plane(v, 0);
        uint32_t p1 = pack_plane(v, 1);
        int s = k2 >> 3, w_ = k2 & 7;
        int lt_ = w_ & 3, rk = w_ >> 2;
        int wm_ = r >> 5, mf_ = (r >> 4) & 1, h_ = (r >> 3) & 1, lg_ = r & 7;
        int lane_ = 4 * lg_ + lt_;
        int base = ((((s * 2 + wm_) * 2 + mf_) * 2) * 32 + lane_) * 4 + rk * 2 + h_;
        sm[OFF_AF + base] = p0;
        sm[OFF_AF + base + 128] = p1;    // p stride = 32*4
    }

    // ---- B tiles 0,1 via cp.async (straight linear 32KB copies) ----
    {
        const char* s0 = (const char*)g_bf4 + (size_t)(blockIdx.y * TILES) * 32768;
        #pragma unroll
        for (int i = 0; i < 8; i++) {
            int off = (i * NT + tid) * 16;
            cp16(smb + OFF_B * 4 + off, s0 + off);
        }
        CP_COMMIT();
        #pragma unroll
        for (int i = 0; i < 8; i++) {
            int off = (i * NT + tid) * 16;
            cp16(smb + (OFF_B + BBUF_U32) * 4 + off, s0 + 32768 + off);
        }
        CP_COMMIT();
    }

    float* sqs = (float*)(sm + OFF_SQ);

    float mn[4];
    int   mi[4];
    #pragma unroll
    for (int s = 0; s < 4; s++) { mn[s] = 3.402823466e38f; mi[s] = 0; }

    const uint4* AF4 = (const uint4*)(sm + OFF_AF);

    for (int t = 0; t < TILES; t++) {
        const uint4* B4 = (const uint4*)(sm + OFF_B + (t & 1) * BBUF_U32);
        const int cb = col0 + t * NBT;

        if (tid < NBT) sqs[tid] = g_sq[cb + tid];
        if (t + 1 < TILES) { CP_WAIT(1); } else { CP_WAIT(0); }
        __syncthreads();

        float acc[2][4][4];
        #pragma unroll
        for (int mf = 0; mf < 2; mf++)
            #pragma unroll
            for (int nf = 0; nf < 4; nf++)
                #pragma unroll
                for (int r = 0; r < 4; r++) acc[mf][nf][r] = 0.f;

        #pragma unroll
        for (int s = 0; s < 4; s++) {
            uint4 a[2][2];   // [plane][mf]
            #pragma unroll
            for (int mf = 0; mf < 2; mf++)
                #pragma unroll
                for (int p = 0; p < 2; p++)
                    a[p][mf] = AF4[(((s * 2 + wm) * 2 + mf) * 2 + p) * 32 + lane];
            uint4 bb[2][2];  // [plane][nfpair]
            #pragma unroll
            for (int p = 0; p < 2; p++)
                #pragma unroll
                for (int pp = 0; pp < 2; pp++)
                    bb[p][pp] = B4[((s * 2 + p) * 8 + wn * 2 + pp) * 32 + lane];

            // products h0h0, h0h1, h1h0 (h1h1 dropped: ~2^-22)
            #pragma unroll
            for (int mf = 0; mf < 2; mf++)
                #pragma unroll
                for (int nf = 0; nf < 4; nf++) {
                    const uint4& B = bb[0][nf >> 1];
                    MMA16(acc[mf][nf], a[0][mf], (nf & 1) ? B.z : B.x, (nf & 1) ? B.w : B.y);
                }
            #pragma unroll
            for (int mf = 0; mf < 2; mf++)
                #pragma unroll
                for (int nf = 0; nf < 4; nf++) {
                    const uint4& B = bb[1][nf >> 1];
                    MMA16(acc[mf][nf], a[0][mf], (nf & 1) ? B.z : B.x, (nf & 1) ? B.w : B.y);
                }
            #pragma unroll
            for (int mf = 0; mf < 2; mf++)
                #pragma unroll
                for (int nf = 0; nf < 4; nf++) {
                    const uint4& B = bb[0][nf >> 1];
                    MMA16(acc[mf][nf], a[1][mf], (nf & 1) ? B.z : B.x, (nf & 1) ? B.w : B.y);
                }
        }

        // ---- epilogue: argmin of (sb - 2*dot); self excluded ----
        #pragma unroll
        for (int mf = 0; mf < 2; mf++) {
            const int ig = row0 + wm * 32 + mf * 16 + lg;   // +8 for h=1
            #pragma unroll
            for (int nf = 0; nf < 4; nf++) {
                const int lc = wn * 32 + nf * 8 + 2 * lt;
                const float sb0 = sqs[lc], sb1 = sqs[lc + 1];
                const int j0 = cb + lc, j1 = j0 + 1;
                float v;
                v = fmaf(-2.f, acc[mf][nf][0], sb0);
                if (j0 != ig && v < mn[mf * 2]) { mn[mf * 2] = v; mi[mf * 2] = j0; }
                v = fmaf(-2.f, acc[mf][nf][1], sb1);
                if (j1 != ig && v < mn[mf * 2]) { mn[mf * 2] = v; mi[mf * 2] = j1; }
                v = fmaf(-2.f, acc[mf][nf][2], sb0);
                if (j0 != ig + 8 && v < mn[mf * 2 + 1]) { mn[mf * 2 + 1] = v; mi[mf * 2 + 1] = j0; }
                v = fmaf(-2.f, acc[mf][nf][3], sb1);
                if (j1 != ig + 8 && v < mn[mf * 2 + 1]) { mn[mf * 2 + 1] = v; mi[mf * 2 + 1] = j1; }
            }
        }

        // ---- fused zero-fill: warp owns 8 rows, 512B/row wavefront ----
        {
            const float4 z4 = make_float4(0.f, 0.f, 0.f, 0.f);
            float4* p = (float4*)(out + (size_t)(row0 + wid * 8) * NPTS + cb) + lane;
            #pragma unroll
            for (int i = 0; i < 8; i++) {
                *p = z4;
                p += NPTS / 4;
            }
        }

        __syncthreads();
        if (t + 2 < TILES) {
            const char* s2 = (const char*)g_bf4 + (size_t)(blockIdx.y * TILES + t + 2) * 32768;
            #pragma unroll
            for (int i = 0; i < 8; i++) {
                int off = (i * NT + tid) * 16;
                cp16(smb + (OFF_B + (t & 1) * BBUF_U32) * 4 + off, s2 + off);
            }
            CP_COMMIT();
        }
    }

    // ---- cross-warp reduction (16 partials per row), then atomicMin merge ----
    float* redv = (float*)sm;                 // reuse AF region
    int*   redi = (int*)(sm + MB * 16);
    #pragma unroll
    for (int s = 0; s < 4; s++) {
        int rloc = wm * 32 + (s >> 1) * 16 + (s & 1) * 8 + lg;
        redv[rloc * 16 + wn * 4 + lt] = mn[s];
        redi[rloc * 16 + wn * 4 + lt] = mi[s];
    }
    __syncthreads();
    if (tid < MB) {
        float bv = redv[tid * 16];
        int   bi = redi[tid * 16];
        #pragma unroll
        for (int x = 1; x < 16; x++) {
            float v = redv[tid * 16 + x];
            int   i = redi[tid * 16 + x];
            if (v < bv || (v == bv && i < bi)) { bv = v; bi = i; }
        }
        uint32_t b = __float_as_uint(bv);
        b ^= (uint32_t)(((int32_t)b >> 31)) | 0x80000000u;   // monotonic map
        unsigned long long key = ((unsigned long long)b << 32) | (unsigned)bi;
        atomicMin(&g_key[row0 + tid], key);
    }
}

extern "C" void kernel_launch(void* const* d_in, const int* in_sizes, int n_in,
                              void* d_out, int out_size) {
    const float* X = (const float*)d_in[0];
    float* out = (float*)d_out;
    cudaFuncSetAttribute(knn_kernel, cudaFuncAttributeMaxDynamicSharedMemorySize, SMEM_BYTES);
    sq_kernel<<<NPTS / 8, 256>>>(X);
    prep_b<<<1024, 256>>>(X);
    init_kernel<<<NPTS / 256, 256>>>();
    knn_kernel<<<dim3(NPTS / MB, NCHUNK), NT, SMEM_BYTES>>>(X, out);
    final_kernel<<<NPTS / 256, 256>>>(out);
}